// round 1
// baseline (speedup 1.0000x reference)
#include <cuda_runtime.h>
#include <cuda_bf16.h>

// Problem constants
#define NTOK   10000
#define EMB    100
#define SEQT   80
#define UNITS  64
#define BATCH  8192
#define TILE_B 64
#define THREADS 256
#define NBLK   (BATCH / TILE_B)   // 128

// Precomputed emb @ W1x + b1  (scratch: device global, no allocation)
__device__ float g_embW[NTOK * UNITS];

// ---------- packed f32x2 helpers ----------
__device__ __forceinline__ unsigned long long ffma2(unsigned long long a,
                                                    unsigned long long b,
                                                    unsigned long long c) {
    unsigned long long d;
    asm("fma.rn.f32x2 %0, %1, %2, %3;" : "=l"(d) : "l"(a), "l"(b), "l"(c));
    return d;
}
__device__ __forceinline__ unsigned long long dup2(float x) {
    unsigned long long d;
    asm("mov.b64 %0, {%1, %1};" : "=l"(d) : "r"(__float_as_uint(x)));
    return d;
}
__device__ __forceinline__ unsigned long long pack2(float lo, float hi) {
    unsigned long long d;
    asm("mov.b64 %0, {%1, %2};" : "=l"(d) : "r"(__float_as_uint(lo)), "r"(__float_as_uint(hi)));
    return d;
}
__device__ __forceinline__ float2 unpack2(unsigned long long v) {
    unsigned int lo, hi;
    asm("mov.b64 {%0, %1}, %2;" : "=r"(lo), "=r"(hi) : "l"(v));
    return make_float2(__uint_as_float(lo), __uint_as_float(hi));
}

__device__ __forceinline__ float fast_tanh(float x) {
    float e = __expf(2.0f * x);
    return __fdividef(e - 1.0f, e + 1.0f);
}

// ---------- Kernel 1: embW[v][j] = sum_i emb[v][i] * W1x[i][j] + b1[j] ----------
__global__ void __launch_bounds__(256)
embw_kernel(const float* __restrict__ emb, const float* __restrict__ W1x,
            const float* __restrict__ b1) {
    __shared__ float sW[EMB * UNITS];   // 25.6 KB
    int tid = threadIdx.x;
    for (int i = tid; i < EMB * UNITS; i += 256) sW[i] = W1x[i];
    __syncthreads();

    int j = tid & 63;
    int r = tid >> 6;                   // 0..3
    int v0 = blockIdx.x * 16;
    #pragma unroll
    for (int chunk = 0; chunk < 4; chunk++) {
        int v = v0 + chunk * 4 + r;
        if (v < NTOK) {
            float acc = b1[j];
            const float* er = emb + (long long)v * EMB;
            #pragma unroll 10
            for (int i = 0; i < EMB; i++)
                acc = fmaf(er[i], sW[i * UNITS + j], acc);
            g_embW[v * UNITS + j] = acc;
        }
    }
}

// ---------- Kernel 2: persistent per-batch-tile RNN ----------
// Shared layout (floats):
//   sW1h : [0,      4096)   W1h[k][j]
//   sW2  : [4096,  12288)   rows 0..63 = W2x, rows 64..127 = W2h
//   sH1  : [12288, 20480)   2 x [64][64] swizzled (k-major, q ^= k>>2)
//   sH2  : [20480, 28672)   2 x [64][64] swizzled
//   stok : [28672, 33792)   [t][b] tokens (ints)
#define SMEM_FLOATS 33792
#define SMEM_BYTES  (SMEM_FLOATS * 4)

__global__ void __launch_bounds__(THREADS)
rnn_kernel(const int* __restrict__ tokens,
           const float* __restrict__ W1h,
           const float* __restrict__ W2x,
           const float* __restrict__ W2h,
           const float* __restrict__ b2,
           const float* __restrict__ Wd,
           const float* __restrict__ bd,
           float* __restrict__ out) {
    extern __shared__ float smem[];
    float* sW1h = smem;
    float* sW2  = smem + 4096;
    float* sH1  = smem + 12288;
    float* sH2  = smem + 20480;
    int*   stok = (int*)(smem + 28672);

    const int tid   = threadIdx.x;
    const int jgrp  = tid & 15;         // 16 groups of 4 output cols
    const int bgrp  = tid >> 4;         // 16 groups of 4 batch rows
    const int j0    = jgrp << 2;
    const int b0    = bgrp << 2;
    const int bbase = blockIdx.x * TILE_B;

    // Load weights
    for (int i = tid; i < 4096; i += THREADS) sW1h[i] = W1h[i];
    for (int i = tid; i < 4096; i += THREADS) { sW2[i] = W2x[i]; sW2[4096 + i] = W2h[i]; }
    // Load tokens transposed: stok[t][b]
    for (int idx = tid; idx < TILE_B * SEQT; idx += THREADS) {
        int b = idx / SEQT, t = idx % SEQT;
        stok[t * TILE_B + b] = tokens[(long long)(bbase + b) * SEQT + t];
    }
    // Zero h0 (buffer 0); swizzle irrelevant for zeros
    for (int i = tid; i < 4096; i += THREADS) { sH1[i] = 0.0f; sH2[i] = 0.0f; }
    __syncthreads();

    // b2 pair accumcolumn init (j-pairs), loop-invariant
    const ulonglong2 b2v = *(const ulonglong2*)(b2 + j0);

    // Prefetch g for t=0
    float4 g[4];
    {
        int4 tv = *(const int4*)(stok + b0);
        g[0] = *(const float4*)(g_embW + tv.x * UNITS + j0);
        g[1] = *(const float4*)(g_embW + tv.y * UNITS + j0);
        g[2] = *(const float4*)(g_embW + tv.z * UNITS + j0);
        g[3] = *(const float4*)(g_embW + tv.w * UNITS + j0);
    }

    const int wq = (bgrp ^ jgrp) << 2;  // swizzled write column offset
    int cur = 0;

    for (int t = 0; t < SEQT; t++) {
        const int nxt = cur ^ 1;
        // ---------- Layer 1: C = g + H1[cur] @ W1h ----------
        unsigned long long acc[4][2];
        #pragma unroll
        for (int r = 0; r < 4; r++) {
            acc[r][0] = pack2(((const float*)&g[r])[0], ((const float*)&g[r])[1]);
            acc[r][1] = pack2(((const float*)&g[r])[2], ((const float*)&g[r])[3]);
        }
        {
            const float* A = sH1 + cur * 4096;
            #pragma unroll 8
            for (int k = 0; k < UNITS; k++) {
                float4 av = *(const float4*)(A + k * UNITS + ((bgrp ^ (k >> 2)) << 2));
                ulonglong2 wv = *(const ulonglong2*)(sW1h + k * UNITS + j0);
                unsigned long long a0 = dup2(av.x), a1 = dup2(av.y), a2 = dup2(av.z), a3 = dup2(av.w);
                acc[0][0] = ffma2(a0, wv.x, acc[0][0]); acc[0][1] = ffma2(a0, wv.y, acc[0][1]);
                acc[1][0] = ffma2(a1, wv.x, acc[1][0]); acc[1][1] = ffma2(a1, wv.y, acc[1][1]);
                acc[2][0] = ffma2(a2, wv.x, acc[2][0]); acc[2][1] = ffma2(a2, wv.y, acc[2][1]);
                acc[3][0] = ffma2(a3, wv.x, acc[3][0]); acc[3][1] = ffma2(a3, wv.y, acc[3][1]);
            }
        }
        // tanh + swizzled store into H1[nxt]
        {
            float th[4][4];
            #pragma unroll
            for (int r = 0; r < 4; r++) {
                float2 lo = unpack2(acc[r][0]), hi = unpack2(acc[r][1]);
                th[r][0] = fast_tanh(lo.x); th[r][1] = fast_tanh(lo.y);
                th[r][2] = fast_tanh(hi.x); th[r][3] = fast_tanh(hi.y);
            }
            float* D = sH1 + nxt * 4096;
            #pragma unroll
            for (int rr = 0; rr < 4; rr++)
                *(float4*)(D + (j0 + rr) * UNITS + wq) =
                    make_float4(th[0][rr], th[1][rr], th[2][rr], th[3][rr]);
        }
        __syncthreads();

        // Prefetch g for t+1 (overlaps layer-2 compute)
        if (t + 1 < SEQT) {
            int4 tv = *(const int4*)(stok + (t + 1) * TILE_B + b0);
            g[0] = *(const float4*)(g_embW + tv.x * UNITS + j0);
            g[1] = *(const float4*)(g_embW + tv.y * UNITS + j0);
            g[2] = *(const float4*)(g_embW + tv.z * UNITS + j0);
            g[3] = *(const float4*)(g_embW + tv.w * UNITS + j0);
        }

        // ---------- Layer 2: C = b2 + H1[nxt] @ W2x + H2[cur] @ W2h ----------
        #pragma unroll
        for (int r = 0; r < 4; r++) { acc[r][0] = b2v.x; acc[r][1] = b2v.y; }
        {
            const float* A = sH1 + nxt * 4096;
            #pragma unroll 8
            for (int k = 0; k < UNITS; k++) {
                float4 av = *(const float4*)(A + k * UNITS + ((bgrp ^ (k >> 2)) << 2));
                ulonglong2 wv = *(const ulonglong2*)(sW2 + k * UNITS + j0);
                unsigned long long a0 = dup2(av.x), a1 = dup2(av.y), a2 = dup2(av.z), a3 = dup2(av.w);
                acc[0][0] = ffma2(a0, wv.x, acc[0][0]); acc[0][1] = ffma2(a0, wv.y, acc[0][1]);
                acc[1][0] = ffma2(a1, wv.x, acc[1][0]); acc[1][1] = ffma2(a1, wv.y, acc[1][1]);
                acc[2][0] = ffma2(a2, wv.x, acc[2][0]); acc[2][1] = ffma2(a2, wv.y, acc[2][1]);
                acc[3][0] = ffma2(a3, wv.x, acc[3][0]); acc[3][1] = ffma2(a3, wv.y, acc[3][1]);
            }
            const float* A2 = sH2 + cur * 4096;
            #pragma unroll 8
            for (int k = 0; k < UNITS; k++) {
                float4 av = *(const float4*)(A2 + k * UNITS + ((bgrp ^ (k >> 2)) << 2));
                ulonglong2 wv = *(const ulonglong2*)(sW2 + (UNITS + k) * UNITS + j0);
                unsigned long long a0 = dup2(av.x), a1 = dup2(av.y), a2 = dup2(av.z), a3 = dup2(av.w);
                acc[0][0] = ffma2(a0, wv.x, acc[0][0]); acc[0][1] = ffma2(a0, wv.y, acc[0][1]);
                acc[1][0] = ffma2(a1, wv.x, acc[1][0]); acc[1][1] = ffma2(a1, wv.y, acc[1][1]);
                acc[2][0] = ffma2(a2, wv.x, acc[2][0]); acc[2][1] = ffma2(a2, wv.y, acc[2][1]);
                acc[3][0] = ffma2(a3, wv.x, acc[3][0]); acc[3][1] = ffma2(a3, wv.y, acc[3][1]);
            }
        }
        // tanh + swizzled store into H2[nxt]
        {
            float th[4][4];
            #pragma unroll
            for (int r = 0; r < 4; r++) {
                float2 lo = unpack2(acc[r][0]), hi = unpack2(acc[r][1]);
                th[r][0] = fast_tanh(lo.x); th[r][1] = fast_tanh(lo.y);
                th[r][2] = fast_tanh(hi.x); th[r][3] = fast_tanh(hi.y);
            }
            float* D = sH2 + nxt * 4096;
            #pragma unroll
            for (int rr = 0; rr < 4; rr++)
                *(float4*)(D + (j0 + rr) * UNITS + wq) =
                    make_float4(th[0][rr], th[1][rr], th[2][rr], th[3][rr]);
        }
        __syncthreads();
        cur = nxt;
    }

    // ---------- Final dense + sigmoid ----------
    if (tid < TILE_B) {
        const int b = tid;
        const float* H = sH2 + cur * 4096;
        float s = bd[0];
        #pragma unroll 8
        for (int k = 0; k < UNITS; k++) {
            int q = (((b >> 2) ^ (k >> 2)) << 2) | (b & 3);
            s = fmaf(H[k * UNITS + q], Wd[k], s);
        }
        out[bbase + b] = __fdividef(1.0f, 1.0f + __expf(-s));
    }
}

extern "C" void kernel_launch(void* const* d_in, const int* in_sizes, int n_in,
                              void* d_out, int out_size) {
    const int*   tokens = (const int*)  d_in[0];
    const float* emb    = (const float*)d_in[1];
    const float* W1x    = (const float*)d_in[2];
    const float* W1h    = (const float*)d_in[3];
    const float* b1     = (const float*)d_in[4];
    const float* W2x    = (const float*)d_in[5];
    const float* W2h    = (const float*)d_in[6];
    const float* b2     = (const float*)d_in[7];
    const float* Wd     = (const float*)d_in[8];
    const float* bd     = (const float*)d_in[9];

    cudaFuncSetAttribute(rnn_kernel, cudaFuncAttributeMaxDynamicSharedMemorySize, SMEM_BYTES);

    embw_kernel<<<(NTOK + 15) / 16, 256>>>(emb, W1x, b1);
    rnn_kernel<<<NBLK, THREADS, SMEM_BYTES>>>(tokens, W1h, W2x, W2h, b2, Wd, bd,
                                              (float*)d_out);
}

// round 2
// speedup vs baseline: 1.0080x; 1.0080x over previous
#include <cuda_runtime.h>
#include <cuda_bf16.h>

// Problem constants
#define NTOK   10000
#define EMB    100
#define SEQT   80
#define UNITS  64
#define BATCH  8192
#define TILE_B 64
#define THREADS 512
#define NBLK   (BATCH / TILE_B)   // 128

// Precomputed emb @ W1x + b1  (scratch: device global, no allocation)
__device__ float g_embW[NTOK * UNITS];

// ---------- packed f32x2 helpers ----------
__device__ __forceinline__ unsigned long long ffma2(unsigned long long a,
                                                    unsigned long long b,
                                                    unsigned long long c) {
    unsigned long long d;
    asm("fma.rn.f32x2 %0, %1, %2, %3;" : "=l"(d) : "l"(a), "l"(b), "l"(c));
    return d;
}
__device__ __forceinline__ unsigned long long dup2(float x) {
    unsigned long long d;
    asm("mov.b64 %0, {%1, %1};" : "=l"(d) : "r"(__float_as_uint(x)));
    return d;
}
__device__ __forceinline__ unsigned long long pack2(float lo, float hi) {
    unsigned long long d;
    asm("mov.b64 %0, {%1, %2};" : "=l"(d) : "r"(__float_as_uint(lo)), "r"(__float_as_uint(hi)));
    return d;
}
__device__ __forceinline__ float2 unpack2(unsigned long long v) {
    unsigned int lo, hi;
    asm("mov.b64 {%0, %1}, %2;" : "=r"(lo), "=r"(hi) : "l"(v));
    return make_float2(__uint_as_float(lo), __uint_as_float(hi));
}

__device__ __forceinline__ float fast_tanh(float x) {
    float e = __expf(2.0f * x);
    return __fdividef(e - 1.0f, e + 1.0f);
}

// ---------- Kernel 1: embW[v][j] = sum_i emb[v][i] * W1x[i][j] + b1[j] ----------
__global__ void __launch_bounds__(256)
embw_kernel(const float* __restrict__ emb, const float* __restrict__ W1x,
            const float* __restrict__ b1) {
    __shared__ float sW[EMB * UNITS];   // 25.6 KB
    int tid = threadIdx.x;
    for (int i = tid; i < EMB * UNITS; i += 256) sW[i] = W1x[i];
    __syncthreads();

    int j = tid & 63;
    int r = tid >> 6;                   // 0..3
    int v0 = blockIdx.x * 16;
    #pragma unroll
    for (int chunk = 0; chunk < 4; chunk++) {
        int v = v0 + chunk * 4 + r;
        if (v < NTOK) {
            float acc = b1[j];
            const float* er = emb + (long long)v * EMB;
            #pragma unroll 10
            for (int i = 0; i < EMB; i++)
                acc = fmaf(er[i], sW[i * UNITS + j], acc);
            g_embW[v * UNITS + j] = acc;
        }
    }
}

// ---------- Kernel 2: persistent per-batch-tile RNN, pipelined warpgroups ----------
// Warps 0-7  (group A): layer 1 for step t = s
// Warps 8-15 (group B): layer 2 for step t = s-1
// One __syncthreads per pipeline slot. 81 slots total.
//
// Shared layout (floats):
//   sW1h : [0,      4096)   W1h[k][j]
//   sW2  : [4096,  12288)   rows 0..63 = W2x, rows 64..127 = W2h
//   sH1  : [12288, 20480)   2 x [64 k][64 b] swizzled (q ^= k>>2 quad)
//   sH2  : [20480, 28672)   2 x [64 k][64 b] swizzled
//   stok : [28672, 33792)   [t][b] tokens (ints)
#define SMEM_FLOATS 33792
#define SMEM_BYTES  (SMEM_FLOATS * 4)

__global__ void __launch_bounds__(THREADS)
rnn_kernel(const int* __restrict__ tokens,
           const float* __restrict__ W1h,
           const float* __restrict__ W2x,
           const float* __restrict__ W2h,
           const float* __restrict__ b2,
           const float* __restrict__ Wd,
           const float* __restrict__ bd,
           float* __restrict__ out) {
    extern __shared__ float smem[];
    float* sW1h = smem;
    float* sW2  = smem + 4096;
    float* sH1  = smem + 12288;
    float* sH2  = smem + 20480;
    int*   stok = (int*)(smem + 28672);

    const int tid   = threadIdx.x;
    const bool isA  = (tid < 256);
    const int tg    = tid & 255;
    const int jgrp  = tg & 15;          // 16 groups of 4 output cols
    const int bgrp  = tg >> 4;          // 16 groups of 4 batch rows
    const int j0    = jgrp << 2;
    const int b0    = bgrp << 2;
    const int wq    = (bgrp ^ jgrp) << 2;   // swizzled write column offset
    const int bbase = blockIdx.x * TILE_B;

    // Cooperative loads (all 512 threads)
    for (int i = tid; i < 4096; i += THREADS) sW1h[i] = W1h[i];
    for (int i = tid; i < 4096; i += THREADS) { sW2[i] = W2x[i]; sW2[4096 + i] = W2h[i]; }
    for (int idx = tid; idx < TILE_B * SEQT; idx += THREADS) {
        int b = idx / SEQT, t = idx % SEQT;
        stok[t * TILE_B + b] = tokens[(long long)(bbase + b) * SEQT + t];
    }
    for (int i = tid; i < 8192; i += THREADS) { sH1[i] = 0.0f; sH2[i] = 0.0f; }
    __syncthreads();

    float4 g[4];
    ulonglong2 b2v;
    if (isA) {
        // Prefetch g for t=0
        int4 tv = *(const int4*)(stok + b0);
        g[0] = *(const float4*)(g_embW + tv.x * UNITS + j0);
        g[1] = *(const float4*)(g_embW + tv.y * UNITS + j0);
        g[2] = *(const float4*)(g_embW + tv.z * UNITS + j0);
        g[3] = *(const float4*)(g_embW + tv.w * UNITS + j0);
    } else {
        b2v = *(const ulonglong2*)(b2 + j0);
    }

    for (int s = 0; s <= SEQT; s++) {
        if (isA) {
            if (s < SEQT) {
                // ---------- Layer 1, t = s: C = g + H1[s-1] @ W1h ----------
                unsigned long long acc[4][2];
                #pragma unroll
                for (int r = 0; r < 4; r++) {
                    acc[r][0] = pack2(((const float*)&g[r])[0], ((const float*)&g[r])[1]);
                    acc[r][1] = pack2(((const float*)&g[r])[2], ((const float*)&g[r])[3]);
                }
                // Prefetch g for t = s+1 (completes during the GEMM below)
                if (s + 1 < SEQT) {
                    int4 tv = *(const int4*)(stok + (s + 1) * TILE_B + b0);
                    g[0] = *(const float4*)(g_embW + tv.x * UNITS + j0);
                    g[1] = *(const float4*)(g_embW + tv.y * UNITS + j0);
                    g[2] = *(const float4*)(g_embW + tv.z * UNITS + j0);
                    g[3] = *(const float4*)(g_embW + tv.w * UNITS + j0);
                }
                const float* Ap = sH1 + ((s & 1) ^ 1) * 4096;
                #pragma unroll 8
                for (int k = 0; k < UNITS; k++) {
                    float4 av = *(const float4*)(Ap + k * UNITS + ((bgrp ^ (k >> 2)) << 2));
                    ulonglong2 wv = *(const ulonglong2*)(sW1h + k * UNITS + j0);
                    unsigned long long a0 = dup2(av.x), a1 = dup2(av.y), a2 = dup2(av.z), a3 = dup2(av.w);
                    acc[0][0] = ffma2(a0, wv.x, acc[0][0]); acc[0][1] = ffma2(a0, wv.y, acc[0][1]);
                    acc[1][0] = ffma2(a1, wv.x, acc[1][0]); acc[1][1] = ffma2(a1, wv.y, acc[1][1]);
                    acc[2][0] = ffma2(a2, wv.x, acc[2][0]); acc[2][1] = ffma2(a2, wv.y, acc[2][1]);
                    acc[3][0] = ffma2(a3, wv.x, acc[3][0]); acc[3][1] = ffma2(a3, wv.y, acc[3][1]);
                }
                float th[4][4];
                #pragma unroll
                for (int r = 0; r < 4; r++) {
                    float2 lo = unpack2(acc[r][0]), hi = unpack2(acc[r][1]);
                    th[r][0] = fast_tanh(lo.x); th[r][1] = fast_tanh(lo.y);
                    th[r][2] = fast_tanh(hi.x); th[r][3] = fast_tanh(hi.y);
                }
                float* D = sH1 + (s & 1) * 4096;
                #pragma unroll
                for (int rr = 0; rr < 4; rr++)
                    *(float4*)(D + (j0 + rr) * UNITS + wq) =
                        make_float4(th[0][rr], th[1][rr], th[2][rr], th[3][rr]);
            }
        } else {
            if (s >= 1) {
                // ---------- Layer 2, t = s-1: C = b2 + H1[t] @ W2x + H2[t-1] @ W2h ----------
                const int par = (s & 1) ^ 1;                 // t & 1
                unsigned long long acc[4][2];
                #pragma unroll
                for (int r = 0; r < 4; r++) { acc[r][0] = b2v.x; acc[r][1] = b2v.y; }
                const float* A1 = sH1 + par * 4096;
                #pragma unroll 8
                for (int k = 0; k < UNITS; k++) {
                    float4 av = *(const float4*)(A1 + k * UNITS + ((bgrp ^ (k >> 2)) << 2));
                    ulonglong2 wv = *(const ulonglong2*)(sW2 + k * UNITS + j0);
                    unsigned long long a0 = dup2(av.x), a1 = dup2(av.y), a2 = dup2(av.z), a3 = dup2(av.w);
                    acc[0][0] = ffma2(a0, wv.x, acc[0][0]); acc[0][1] = ffma2(a0, wv.y, acc[0][1]);
                    acc[1][0] = ffma2(a1, wv.x, acc[1][0]); acc[1][1] = ffma2(a1, wv.y, acc[1][1]);
                    acc[2][0] = ffma2(a2, wv.x, acc[2][0]); acc[2][1] = ffma2(a2, wv.y, acc[2][1]);
                    acc[3][0] = ffma2(a3, wv.x, acc[3][0]); acc[3][1] = ffma2(a3, wv.y, acc[3][1]);
                }
                const float* A2 = sH2 + (s & 1) * 4096;      // (t-1) & 1
                #pragma unroll 8
                for (int k = 0; k < UNITS; k++) {
                    float4 av = *(const float4*)(A2 + k * UNITS + ((bgrp ^ (k >> 2)) << 2));
                    ulonglong2 wv = *(const ulonglong2*)(sW2 + (UNITS + k) * UNITS + j0);
                    unsigned long long a0 = dup2(av.x), a1 = dup2(av.y), a2 = dup2(av.z), a3 = dup2(av.w);
                    acc[0][0] = ffma2(a0, wv.x, acc[0][0]); acc[0][1] = ffma2(a0, wv.y, acc[0][1]);
                    acc[1][0] = ffma2(a1, wv.x, acc[1][0]); acc[1][1] = ffma2(a1, wv.y, acc[1][1]);
                    acc[2][0] = ffma2(a2, wv.x, acc[2][0]); acc[2][1] = ffma2(a2, wv.y, acc[2][1]);
                    acc[3][0] = ffma2(a3, wv.x, acc[3][0]); acc[3][1] = ffma2(a3, wv.y, acc[3][1]);
                }
                float th[4][4];
                #pragma unroll
                for (int r = 0; r < 4; r++) {
                    float2 lo = unpack2(acc[r][0]), hi = unpack2(acc[r][1]);
                    th[r][0] = fast_tanh(lo.x); th[r][1] = fast_tanh(lo.y);
                    th[r][2] = fast_tanh(hi.x); th[r][3] = fast_tanh(hi.y);
                }
                float* D = sH2 + par * 4096;
                #pragma unroll
                for (int rr = 0; rr < 4; rr++)
                    *(float4*)(D + (j0 + rr) * UNITS + wq) =
                        make_float4(th[0][rr], th[1][rr], th[2][rr], th[3][rr]);
            }
        }
        __syncthreads();
    }

    // ---------- Final dense + sigmoid (group B, h2[79] is in buffer 1) ----------
    if (!isA && tg < TILE_B) {
        const int b = tg;
        const float* H = sH2 + 4096;    // 79 & 1 == 1
        float sum = bd[0];
        #pragma unroll 8
        for (int k = 0; k < UNITS; k++) {
            int q = (((b >> 2) ^ (k >> 2)) << 2) | (b & 3);
            sum = fmaf(H[k * UNITS + q], Wd[k], sum);
        }
        out[bbase + b] = __fdividef(1.0f, 1.0f + __expf(-sum));
    }
}

extern "C" void kernel_launch(void* const* d_in, const int* in_sizes, int n_in,
                              void* d_out, int out_size) {
    const int*   tokens = (const int*)  d_in[0];
    const float* emb    = (const float*)d_in[1];
    const float* W1x    = (const float*)d_in[2];
    const float* W1h    = (const float*)d_in[3];
    const float* b1     = (const float*)d_in[4];
    const float* W2x    = (const float*)d_in[5];
    const float* W2h    = (const float*)d_in[6];
    const float* b2     = (const float*)d_in[7];
    const float* Wd     = (const float*)d_in[8];
    const float* bd     = (const float*)d_in[9];

    cudaFuncSetAttribute(rnn_kernel, cudaFuncAttributeMaxDynamicSharedMemorySize, SMEM_BYTES);

    embw_kernel<<<(NTOK + 15) / 16, 256>>>(emb, W1x, b1);
    rnn_kernel<<<NBLK, THREADS, SMEM_BYTES>>>(tokens, W1h, W2x, W2h, b2, Wd, bd,
                                              (float*)d_out);
}

// round 7
// speedup vs baseline: 2.8712x; 2.8485x over previous
#include <cuda_runtime.h>
#include <cuda_bf16.h>
#include <cstdint>

// Problem constants
#define NTOK   10000
#define EMB    100
#define SEQT   80
#define UNITS  64
#define BATCH  8192
#define TILE_B 64
#define NBLK   (BATCH / TILE_B)   // 128
#define THREADS 256

// Precomputed emb @ W1x + b1  (fp32 scratch)
__device__ float g_embW[NTOK * UNITS];

// ---------------- helpers ----------------
__device__ __forceinline__ uint32_t swz(uint32_t off) {           // SW128 swizzle
    return off ^ ((off >> 3) & 0x70);
}
__device__ __forceinline__ uint32_t smem_u32(const void* p) {
    uint32_t a;
    asm("{ .reg .u64 t; cvta.to.shared.u64 t, %1; cvt.u32.u64 %0, t; }" : "=r"(a) : "l"(p));
    return a;
}
__device__ __forceinline__ void ldsm4(uint32_t r[4], uint32_t addr) {
    asm volatile("ldmatrix.sync.aligned.m8n8.x4.shared.b16 {%0,%1,%2,%3}, [%4];"
                 : "=r"(r[0]), "=r"(r[1]), "=r"(r[2]), "=r"(r[3]) : "r"(addr));
}
__device__ __forceinline__ void ldsm4t(uint32_t r[4], uint32_t addr) {
    asm volatile("ldmatrix.sync.aligned.m8n8.x4.trans.shared.b16 {%0,%1,%2,%3}, [%4];"
                 : "=r"(r[0]), "=r"(r[1]), "=r"(r[2]), "=r"(r[3]) : "r"(addr));
}
__device__ __forceinline__ void mma16816(float c[4], const uint32_t a[4], const uint32_t b[2]) {
    asm volatile(
        "mma.sync.aligned.m16n8k16.row.col.f32.bf16.bf16.f32 "
        "{%0,%1,%2,%3}, {%4,%5,%6,%7}, {%8,%9}, {%0,%1,%2,%3};"
        : "+f"(c[0]), "+f"(c[1]), "+f"(c[2]), "+f"(c[3])
        : "r"(a[0]), "r"(a[1]), "r"(a[2]), "r"(a[3]), "r"(b[0]), "r"(b[1]));
}
__device__ __forceinline__ void sts32(uint32_t addr, uint32_t v) {
    asm volatile("st.shared.b32 [%0], %1;" :: "r"(addr), "r"(v) : "memory");
}
__device__ __forceinline__ float tanha(float x) {
    float y;
    asm("tanh.approx.f32 %0, %1;" : "=f"(y) : "f"(x));
    return y;
}
__device__ __forceinline__ uint32_t pack_bf16x2(float lo, float hi) {
    uint32_t r;
    asm("cvt.rn.bf16x2.f32 %0, %1, %2;" : "=r"(r) : "f"(hi), "f"(lo));
    return r;
}

// ---------- Kernel 1: embW[v][j] = sum_i emb[v][i] * W1x[i][j] + b1[j] ----------
__global__ void __launch_bounds__(256)
embw_kernel(const float* __restrict__ emb, const float* __restrict__ W1x,
            const float* __restrict__ b1) {
    __shared__ float sW[EMB * UNITS];
    int tid = threadIdx.x;
    for (int i = tid; i < EMB * UNITS; i += 256) sW[i] = W1x[i];
    __syncthreads();
    int j = tid & 63;
    int r = tid >> 6;
    int v0 = blockIdx.x * 64;
    #pragma unroll
    for (int chunk = 0; chunk < 16; chunk++) {
        int v = v0 + chunk * 4 + r;
        if (v < NTOK) {
            float acc = b1[j];
            const float* er = emb + (long long)v * EMB;
            #pragma unroll 10
            for (int i = 0; i < EMB; i++)
                acc = fmaf(er[i], sW[i * UNITS + j], acc);
            g_embW[v * UNITS + j] = acc;
        }
    }
}

// ---------- Kernel 2: mma.sync RNN ----------
// Shared: 3 weight tiles + h1 + h2, all [64 rows][64 bf16 cols] = 128B rows, SW128.
struct __align__(1024) Sm {
    __nv_bfloat16 w[3][4096];   // W1h, W2x, W2h  as B = W[k][j], k-major
    __nv_bfloat16 h1[4096];     // h1[row=batch][col=k]
    __nv_bfloat16 h2[4096];
    float red[TILE_B];
};

__global__ void __launch_bounds__(THREADS)
rnn_kernel(const int* __restrict__ tokens,
           const float* __restrict__ W1h,
           const float* __restrict__ W2x,
           const float* __restrict__ W2h,
           const float* __restrict__ b2,
           const float* __restrict__ Wd,
           const float* __restrict__ bd,
           float* __restrict__ out) {
    __shared__ Sm sm;

    const int tid  = threadIdx.x;
    const int wid  = tid >> 5;
    const int lane = tid & 31;
    const int r0   = (wid & 3) * 16;       // warp's 16 output rows (batch)
    const int c0w  = (wid >> 2) * 32;      // warp's 32 output cols
    const int gid  = lane >> 2;            // groupID
    const int cp   = lane & 3;             // threadID-in-group
    const int row_lo = r0 + gid;
    const int row_hi = row_lo + 8;
    const int bbase  = blockIdx.x * TILE_B;

    // ---- stage weights into shared (bf16, SW128 swizzled, k-major [k][j]) ----
    {
        const float* src[3] = {W1h, W2x, W2h};
        #pragma unroll
        for (int m = 0; m < 3; m++)
            for (int idx = tid; idx < UNITS * UNITS; idx += THREADS) {
                int k = idx >> 6, j = idx & 63;
                uint32_t sw = swz((uint32_t)(k * 128 + j * 2));
                *(__nv_bfloat16*)((char*)sm.w[m] + sw) = __float2bfloat16(src[m][idx]);
            }
    }
    __syncthreads();

    // ---- preload all weight B-fragments into registers (loop-invariant) ----
    uint32_t w1b[4][4][2], w2xb[4][4][2], w2hb[4][4][2];
    {
        const uint32_t bw[3] = {smem_u32(sm.w[0]), smem_u32(sm.w[1]), smem_u32(sm.w[2])};
        #pragma unroll
        for (int kk = 0; kk < 4; kk++)
            #pragma unroll
            for (int np = 0; np < 2; np++) {
                uint32_t off = swz((uint32_t)((kk * 16 + (lane & 15)) * 128 +
                                              (c0w + np * 16 + (lane >> 4) * 8) * 2));
                uint32_t r[4];
                ldsm4t(r, bw[0] + off);
                w1b[kk][np*2][0] = r[0]; w1b[kk][np*2][1] = r[1];
                w1b[kk][np*2+1][0] = r[2]; w1b[kk][np*2+1][1] = r[3];
                ldsm4t(r, bw[1] + off);
                w2xb[kk][np*2][0] = r[0]; w2xb[kk][np*2][1] = r[1];
                w2xb[kk][np*2+1][0] = r[2]; w2xb[kk][np*2+1][1] = r[3];
                ldsm4t(r, bw[2] + off);
                w2hb[kk][np*2][0] = r[0]; w2hb[kk][np*2][1] = r[1];
                w2hb[kk][np*2+1][0] = r[2]; w2hb[kk][np*2+1][1] = r[3];
            }
    }

    // ---- loop-invariant addresses ----
    const uint32_t bh1 = smem_u32(sm.h1);
    const uint32_t bh2 = smem_u32(sm.h2);
    uint32_t aA1[4], aA2[4];
    #pragma unroll
    for (int kk = 0; kk < 4; kk++) {
        uint32_t off = swz((uint32_t)((r0 + (lane & 15)) * 128 + (kk * 2 + (lane >> 4)) * 16));
        aA1[kk] = bh1 + off;
        aA2[kk] = bh2 + off;
    }
    uint32_t st1l[4], st1h[4], st2l[4], st2h[4];
    int gcol[4];
    float2 b2p[4], wdp[4];
    #pragma unroll
    for (int j = 0; j < 4; j++) {
        int col = c0w + j * 8 + cp * 2;
        gcol[j] = col;
        uint32_t ol = swz((uint32_t)(row_lo * 128 + col * 2));
        uint32_t oh = swz((uint32_t)(row_hi * 128 + col * 2));
        st1l[j] = bh1 + ol; st1h[j] = bh1 + oh;
        st2l[j] = bh2 + ol; st2h[j] = bh2 + oh;
        b2p[j] = make_float2(b2[col], b2[col + 1]);
        wdp[j] = make_float2(Wd[col], Wd[col + 1]);
    }

    const int* tok_lo = tokens + (long long)(bbase + row_lo) * SEQT;
    const int* tok_hi = tokens + (long long)(bbase + row_hi) * SEQT;

    // ---- h-state A fragments (zero-initialized h(-1)) ----
    uint32_t A1f[4][4] = {}, A2f[4][4] = {};

    // ---- prefetch g(0) ----
    float2 gl[4], gh[4];
    {
        const float* pl = g_embW + (long long)tok_lo[0] * UNITS;
        const float* ph = g_embW + (long long)tok_hi[0] * UNITS;
        #pragma unroll
        for (int j = 0; j < 4; j++) {
            gl[j] = *(const float2*)(pl + gcol[j]);
            gh[j] = *(const float2*)(ph + gcol[j]);
        }
    }

    float p_lo = 0.0f, p_hi = 0.0f;

    #pragma unroll 1
    for (int t = 0; t < SEQT; t++) {
        // ---------- Phase 1: h1(t) = tanh(g(t) + h1(t-1) @ W1h) ----------
        float c[4][4];
        #pragma unroll
        for (int j = 0; j < 4; j++) {
            c[j][0] = gl[j].x; c[j][1] = gl[j].y;
            c[j][2] = gh[j].x; c[j][3] = gh[j].y;
        }
        #pragma unroll
        for (int kk = 0; kk < 4; kk++)
            #pragma unroll
            for (int j = 0; j < 4; j++)
                mma16816(c[j], A1f[kk], w1b[kk][j]);
        #pragma unroll
        for (int j = 0; j < 4; j++) {
            sts32(st1l[j], pack_bf16x2(tanha(c[j][0]), tanha(c[j][1])));
            sts32(st1h[j], pack_bf16x2(tanha(c[j][2]), tanha(c[j][3])));
        }
        __syncthreads();

        // ---------- Phase 2: reload A1 = h1(t) ----------
        #pragma unroll
        for (int kk = 0; kk < 4; kk++) ldsm4(A1f[kk], aA1[kk]);

        // ---------- prefetch g(t+1) ----------
        if (t + 1 < SEQT) {
            const float* pl = g_embW + (long long)tok_lo[t + 1] * UNITS;
            const float* ph = g_embW + (long long)tok_hi[t + 1] * UNITS;
            #pragma unroll
            for (int j = 0; j < 4; j++) {
                gl[j] = *(const float2*)(pl + gcol[j]);
                gh[j] = *(const float2*)(ph + gcol[j]);
            }
        }

        // ---------- Phase 3: h2(t) = tanh(b2 + h1(t)@W2x + h2(t-1)@W2h) ----------
        #pragma unroll
        for (int j = 0; j < 4; j++) { c[j][0] = 0; c[j][1] = 0; c[j][2] = 0; c[j][3] = 0; }
        #pragma unroll
        for (int kk = 0; kk < 4; kk++)
            #pragma unroll
            for (int j = 0; j < 4; j++)
                mma16816(c[j], A1f[kk], w2xb[kk][j]);
        #pragma unroll
        for (int kk = 0; kk < 4; kk++)
            #pragma unroll
            for (int j = 0; j < 4; j++)
                mma16816(c[j], A2f[kk], w2hb[kk][j]);

        if (t < SEQT - 1) {
            #pragma unroll
            for (int j = 0; j < 4; j++) {
                float t0 = tanha(c[j][0] + b2p[j].x);
                float t1 = tanha(c[j][1] + b2p[j].y);
                float t2 = tanha(c[j][2] + b2p[j].x);
                float t3 = tanha(c[j][3] + b2p[j].y);
                sts32(st2l[j], pack_bf16x2(t0, t1));
                sts32(st2h[j], pack_bf16x2(t2, t3));
            }
            __syncthreads();
            // ---------- Phase 4: reload A2 = h2(t) ----------
            #pragma unroll
            for (int kk = 0; kk < 4; kk++) ldsm4(A2f[kk], aA2[kk]);
        } else {
            // final step: dense partial from fp32 values directly
            #pragma unroll
            for (int j = 0; j < 4; j++) {
                float t0 = tanha(c[j][0] + b2p[j].x);
                float t1 = tanha(c[j][1] + b2p[j].y);
                float t2 = tanha(c[j][2] + b2p[j].x);
                float t3 = tanha(c[j][3] + b2p[j].y);
                p_lo = fmaf(t0, wdp[j].x, fmaf(t1, wdp[j].y, p_lo));
                p_hi = fmaf(t2, wdp[j].x, fmaf(t3, wdp[j].y, p_hi));
            }
        }
    }

    // ---- reduce dense partials (atomic-free) ----
    // Sum over cp (lane bits 0-1) inside each warp:
    p_lo += __shfl_xor_sync(0xFFFFFFFF, p_lo, 1);
    p_lo += __shfl_xor_sync(0xFFFFFFFF, p_lo, 2);
    p_hi += __shfl_xor_sync(0xFFFFFFFF, p_hi, 1);
    p_hi += __shfl_xor_sync(0xFFFFFFFF, p_hi, 2);
    // Pass 1: col-half warps (wid 4-7, cols 32-63) store partials.
    __syncthreads();
    if (wid >= 4 && cp == 0) {
        sm.red[row_lo] = p_lo;
        sm.red[row_hi] = p_hi;
    }
    __syncthreads();
    // Pass 2: col-half warps (wid 0-3) add their partials and emit outputs.
    if (wid < 4 && cp == 0) {
        float zlo = p_lo + sm.red[row_lo] + bd[0];
        float zhi = p_hi + sm.red[row_hi] + bd[0];
        out[bbase + row_lo] = __fdividef(1.0f, 1.0f + __expf(-zlo));
        out[bbase + row_hi] = __fdividef(1.0f, 1.0f + __expf(-zhi));
    }
}

extern "C" void kernel_launch(void* const* d_in, const int* in_sizes, int n_in,
                              void* d_out, int out_size) {
    const int*   tokens = (const int*)  d_in[0];
    const float* emb    = (const float*)d_in[1];
    const float* W1x    = (const float*)d_in[2];
    const float* W1h    = (const float*)d_in[3];
    const float* b1     = (const float*)d_in[4];
    const float* W2x    = (const float*)d_in[5];
    const float* W2h    = (const float*)d_in[6];
    const float* b2     = (const float*)d_in[7];
    const float* Wd     = (const float*)d_in[8];
    const float* bd     = (const float*)d_in[9];

    embw_kernel<<<(NTOK + 63) / 64, 256>>>(emb, W1x, b1);
    rnn_kernel<<<NBLK, THREADS>>>(tokens, W1h, W2x, W2h, b2, Wd, bd, (float*)d_out);
}

// round 8
// speedup vs baseline: 5.9436x; 2.0701x over previous
#include <cuda_runtime.h>
#include <cuda_bf16.h>
#include <cstdint>

// Problem constants
#define NTOK   10000
#define EMB    100
#define SEQT   80
#define UNITS  64
#define BATCH  8192
#define TILE_B 64
#define NBLK   (BATCH / TILE_B)   // 128
#define THREADS 256

// Precomputed emb @ W1x + b1  (fp32 scratch)
__device__ float g_embW[NTOK * UNITS];

// ---------------- helpers ----------------
__device__ __forceinline__ uint32_t swz(uint32_t off) {           // SW128 swizzle
    return off ^ ((off >> 3) & 0x70);
}
__device__ __forceinline__ uint32_t smem_u32(const void* p) {
    uint32_t a;
    asm("{ .reg .u64 t; cvta.to.shared.u64 t, %1; cvt.u32.u64 %0, t; }" : "=r"(a) : "l"(p));
    return a;
}
__device__ __forceinline__ void ldsm4(uint32_t r[4], uint32_t addr) {
    asm volatile("ldmatrix.sync.aligned.m8n8.x4.shared.b16 {%0,%1,%2,%3}, [%4];"
                 : "=r"(r[0]), "=r"(r[1]), "=r"(r[2]), "=r"(r[3]) : "r"(addr));
}
__device__ __forceinline__ void ldsm4t(uint32_t r[4], uint32_t addr) {
    asm volatile("ldmatrix.sync.aligned.m8n8.x4.trans.shared.b16 {%0,%1,%2,%3}, [%4];"
                 : "=r"(r[0]), "=r"(r[1]), "=r"(r[2]), "=r"(r[3]) : "r"(addr));
}
__device__ __forceinline__ void mma16816(float c[4], const uint32_t a[4], const uint32_t b[2]) {
    asm volatile(
        "mma.sync.aligned.m16n8k16.row.col.f32.bf16.bf16.f32 "
        "{%0,%1,%2,%3}, {%4,%5,%6,%7}, {%8,%9}, {%0,%1,%2,%3};"
        : "+f"(c[0]), "+f"(c[1]), "+f"(c[2]), "+f"(c[3])
        : "r"(a[0]), "r"(a[1]), "r"(a[2]), "r"(a[3]), "r"(b[0]), "r"(b[1]));
}
__device__ __forceinline__ void sts32(uint32_t addr, uint32_t v) {
    asm volatile("st.shared.b32 [%0], %1;" :: "r"(addr), "r"(v) : "memory");
}
__device__ __forceinline__ void team_bar(int id) {
    asm volatile("bar.sync %0, 128;" :: "r"(id) : "memory");
}
__device__ __forceinline__ float tanha(float x) {
    float y;
    asm("tanh.approx.f32 %0, %1;" : "=f"(y) : "f"(x));
    return y;
}
__device__ __forceinline__ uint32_t pack_bf16x2(float lo, float hi) {
    uint32_t r;
    asm("cvt.rn.bf16x2.f32 %0, %1, %2;" : "=r"(r) : "f"(hi), "f"(lo));
    return r;
}

// ---------- Kernel 1: embW[v][j] = sum_i emb[v][i] * W1x[i][j] + b1[j] ----------
// Coalesced: stage the block's 16 emb rows (1600 contiguous floats) into shared.
__global__ void __launch_bounds__(256)
embw_kernel(const float* __restrict__ emb, const float* __restrict__ W1x,
            const float* __restrict__ b1) {
    __shared__ float sW[EMB * UNITS];   // 25.6 KB
    __shared__ float sE[16 * EMB];      // 6.4 KB
    int tid = threadIdx.x;
    for (int i = tid; i < EMB * UNITS; i += 256) sW[i] = W1x[i];
    int v0 = blockIdx.x * 16;
    const float* esrc = emb + (long long)v0 * EMB;
    for (int i = tid; i < 16 * EMB; i += 256) sE[i] = esrc[i];   // fully coalesced
    __syncthreads();

    int j = tid & 63;
    int r = tid >> 6;                   // 0..3
    #pragma unroll
    for (int chunk = 0; chunk < 4; chunk++) {
        int vl = chunk * 4 + r;
        int v = v0 + vl;
        if (v < NTOK) {
            float acc = b1[j];
            const float* er = sE + vl * EMB;
            #pragma unroll 10
            for (int i = 0; i < EMB; i++)
                acc = fmaf(er[i], sW[i * UNITS + j], acc);
            g_embW[v * UNITS + j] = acc;
        }
    }
}

// ---------- Kernel 2: mma.sync RNN, two independent 4-warp teams ----------
// Team tm (warps 4tm..4tm+3) owns batch rows [32tm, 32tm+32) with its own
// h1/h2 tiles and its own named barrier. SMSP i holds warp i (team0) and
// warp i+4 (team1): the teams interleave to hide each other's latency gaps.
struct __align__(1024) Sm {
    __nv_bfloat16 w[3][4096];       // W1h, W2x, W2h as B = W[k][j], k-major, SW128
    __nv_bfloat16 h1[2][2048];      // per team: [32 rows][64 cols]
    __nv_bfloat16 h2[2][2048];
    float red[2][32];
};

__global__ void __launch_bounds__(THREADS)
rnn_kernel(const int* __restrict__ tokens,
           const float* __restrict__ W1h,
           const float* __restrict__ W2x,
           const float* __restrict__ W2h,
           const float* __restrict__ b2,
           const float* __restrict__ Wd,
           const float* __restrict__ bd,
           float* __restrict__ out) {
    __shared__ Sm sm;

    const int tid  = threadIdx.x;
    const int wid  = tid >> 5;
    const int lane = tid & 31;
    const int tm   = wid >> 2;             // team 0/1
    const int tw   = wid & 3;              // warp within team
    const int r0   = (tw & 1) * 16;        // warp's 16 rows within team tile
    const int c0w  = (tw >> 1) * 32;       // warp's 32 cols
    const int gid  = lane >> 2;
    const int cp   = lane & 3;
    const int row_lo = r0 + gid;           // team-local rows
    const int row_hi = row_lo + 8;
    const int bbase  = blockIdx.x * TILE_B + tm * 32;
    const int barid  = tm + 1;

    // ---- stage weights into shared (bf16, SW128 swizzled, k-major [k][j]) ----
    {
        const float* src[3] = {W1h, W2x, W2h};
        #pragma unroll
        for (int m = 0; m < 3; m++)
            for (int idx = tid; idx < UNITS * UNITS; idx += THREADS) {
                int k = idx >> 6, j = idx & 63;
                uint32_t sw = swz((uint32_t)(k * 128 + j * 2));
                *(__nv_bfloat16*)((char*)sm.w[m] + sw) = __float2bfloat16(src[m][idx]);
            }
    }
    __syncthreads();

    // ---- preload weight B-fragments into registers (loop-invariant) ----
    uint32_t w1b[4][4][2], w2xb[4][4][2], w2hb[4][4][2];
    {
        const uint32_t bw[3] = {smem_u32(sm.w[0]), smem_u32(sm.w[1]), smem_u32(sm.w[2])};
        #pragma unroll
        for (int kk = 0; kk < 4; kk++)
            #pragma unroll
            for (int np = 0; np < 2; np++) {
                uint32_t off = swz((uint32_t)((kk * 16 + (lane & 15)) * 128 +
                                              (c0w + np * 16 + (lane >> 4) * 8) * 2));
                uint32_t r[4];
                ldsm4t(r, bw[0] + off);
                w1b[kk][np*2][0] = r[0]; w1b[kk][np*2][1] = r[1];
                w1b[kk][np*2+1][0] = r[2]; w1b[kk][np*2+1][1] = r[3];
                ldsm4t(r, bw[1] + off);
                w2xb[kk][np*2][0] = r[0]; w2xb[kk][np*2][1] = r[1];
                w2xb[kk][np*2+1][0] = r[2]; w2xb[kk][np*2+1][1] = r[3];
                ldsm4t(r, bw[2] + off);
                w2hb[kk][np*2][0] = r[0]; w2hb[kk][np*2][1] = r[1];
                w2hb[kk][np*2+1][0] = r[2]; w2hb[kk][np*2+1][1] = r[3];
            }
    }

    // ---- loop-invariant addresses (team-local h tiles: 32 rows x 128 B) ----
    const uint32_t bh1 = smem_u32(sm.h1[tm]);
    const uint32_t bh2 = smem_u32(sm.h2[tm]);
    uint32_t aA1[4], aA2[4];
    #pragma unroll
    for (int kk = 0; kk < 4; kk++) {
        uint32_t off = swz((uint32_t)((r0 + (lane & 15)) * 128 + (kk * 2 + (lane >> 4)) * 16));
        aA1[kk] = bh1 + off;
        aA2[kk] = bh2 + off;
    }
    uint32_t st1l[4], st1h[4], st2l[4], st2h[4];
    int gcol[4];
    float2 b2p[4], wdp[4];
    #pragma unroll
    for (int j = 0; j < 4; j++) {
        int col = c0w + j * 8 + cp * 2;
        gcol[j] = col;
        uint32_t ol = swz((uint32_t)(row_lo * 128 + col * 2));
        uint32_t oh = swz((uint32_t)(row_hi * 128 + col * 2));
        st1l[j] = bh1 + ol; st1h[j] = bh1 + oh;
        st2l[j] = bh2 + ol; st2h[j] = bh2 + oh;
        b2p[j] = make_float2(b2[col], b2[col + 1]);
        wdp[j] = make_float2(Wd[col], Wd[col + 1]);
    }

    const int* tok_lo = tokens + (long long)(bbase + row_lo) * SEQT;
    const int* tok_hi = tokens + (long long)(bbase + row_hi) * SEQT;

    // ---- h-state A fragments (zero-initialized h(-1)) ----
    uint32_t A1f[4][4] = {}, A2f[4][4] = {};

    // ---- prefetch g(0) ----
    float2 gl[4], gh[4];
    {
        const float* pl = g_embW + (long long)tok_lo[0] * UNITS;
        const float* ph = g_embW + (long long)tok_hi[0] * UNITS;
        #pragma unroll
        for (int j = 0; j < 4; j++) {
            gl[j] = *(const float2*)(pl + gcol[j]);
            gh[j] = *(const float2*)(ph + gcol[j]);
        }
    }

    float p_lo = 0.0f, p_hi = 0.0f;

    #pragma unroll 1
    for (int t = 0; t < SEQT; t++) {
        // ---------- Phase 1: h1(t) = tanh(g(t) + h1(t-1) @ W1h) ----------
        float c[4][4];
        #pragma unroll
        for (int j = 0; j < 4; j++) {
            c[j][0] = gl[j].x; c[j][1] = gl[j].y;
            c[j][2] = gh[j].x; c[j][3] = gh[j].y;
        }
        #pragma unroll
        for (int kk = 0; kk < 4; kk++)
            #pragma unroll
            for (int j = 0; j < 4; j++)
                mma16816(c[j], A1f[kk], w1b[kk][j]);
        #pragma unroll
        for (int j = 0; j < 4; j++) {
            sts32(st1l[j], pack_bf16x2(tanha(c[j][0]), tanha(c[j][1])));
            sts32(st1h[j], pack_bf16x2(tanha(c[j][2]), tanha(c[j][3])));
        }
        team_bar(barid);

        // ---------- Phase 2: reload A1 = h1(t) ----------
        #pragma unroll
        for (int kk = 0; kk < 4; kk++) ldsm4(A1f[kk], aA1[kk]);

        // ---------- prefetch g(t+1) ----------
        if (t + 1 < SEQT) {
            const float* pl = g_embW + (long long)tok_lo[t + 1] * UNITS;
            const float* ph = g_embW + (long long)tok_hi[t + 1] * UNITS;
            #pragma unroll
            for (int j = 0; j < 4; j++) {
                gl[j] = *(const float2*)(pl + gcol[j]);
                gh[j] = *(const float2*)(ph + gcol[j]);
            }
        }

        // ---------- Phase 3: h2(t) = tanh(b2 + h1(t)@W2x + h2(t-1)@W2h) ----------
        #pragma unroll
        for (int j = 0; j < 4; j++) { c[j][0] = 0; c[j][1] = 0; c[j][2] = 0; c[j][3] = 0; }
        #pragma unroll
        for (int kk = 0; kk < 4; kk++)
            #pragma unroll
            for (int j = 0; j < 4; j++)
                mma16816(c[j], A1f[kk], w2xb[kk][j]);
        #pragma unroll
        for (int kk = 0; kk < 4; kk++)
            #pragma unroll
            for (int j = 0; j < 4; j++)
                mma16816(c[j], A2f[kk], w2hb[kk][j]);

        if (t < SEQT - 1) {
            #pragma unroll
            for (int j = 0; j < 4; j++) {
                float t0 = tanha(c[j][0] + b2p[j].x);
                float t1 = tanha(c[j][1] + b2p[j].y);
                float t2 = tanha(c[j][2] + b2p[j].x);
                float t3 = tanha(c[j][3] + b2p[j].y);
                sts32(st2l[j], pack_bf16x2(t0, t1));
                sts32(st2h[j], pack_bf16x2(t2, t3));
            }
            team_bar(barid);
            // ---------- Phase 4: reload A2 = h2(t) ----------
            #pragma unroll
            for (int kk = 0; kk < 4; kk++) ldsm4(A2f[kk], aA2[kk]);
        } else {
            // final step: dense partial from fp32 values directly
            #pragma unroll
            for (int j = 0; j < 4; j++) {
                float t0 = tanha(c[j][0] + b2p[j].x);
                float t1 = tanha(c[j][1] + b2p[j].y);
                float t2 = tanha(c[j][2] + b2p[j].x);
                float t3 = tanha(c[j][3] + b2p[j].y);
                p_lo = fmaf(t0, wdp[j].x, fmaf(t1, wdp[j].y, p_lo));
                p_hi = fmaf(t2, wdp[j].x, fmaf(t3, wdp[j].y, p_hi));
            }
        }
    }

    // ---- reduce dense partials (atomic-free, per team) ----
    p_lo += __shfl_xor_sync(0xFFFFFFFF, p_lo, 1);
    p_lo += __shfl_xor_sync(0xFFFFFFFF, p_lo, 2);
    p_hi += __shfl_xor_sync(0xFFFFFFFF, p_hi, 1);
    p_hi += __shfl_xor_sync(0xFFFFFFFF, p_hi, 2);
    // Pass 1: col-half warps (tw 2-3, cols 32-63) store partials.
    if (tw >= 2 && cp == 0) {
        sm.red[tm][row_lo] = p_lo;
        sm.red[tm][row_hi] = p_hi;
    }
    team_bar(barid);
    // Pass 2: warps tw 0-1 add their partials and emit outputs.
    if (tw < 2 && cp == 0) {
        float zlo = p_lo + sm.red[tm][row_lo] + bd[0];
        float zhi = p_hi + sm.red[tm][row_hi] + bd[0];
        out[bbase + row_lo] = __fdividef(1.0f, 1.0f + __expf(-zlo));
        out[bbase + row_hi] = __fdividef(1.0f, 1.0f + __expf(-zhi));
    }
}

extern "C" void kernel_launch(void* const* d_in, const int* in_sizes, int n_in,
                              void* d_out, int out_size) {
    const int*   tokens = (const int*)  d_in[0];
    const float* emb    = (const float*)d_in[1];
    const float* W1x    = (const float*)d_in[2];
    const float* W1h    = (const float*)d_in[3];
    const float* b1     = (const float*)d_in[4];
    const float* W2x    = (const float*)d_in[5];
    const float* W2h    = (const float*)d_in[6];
    const float* b2     = (const float*)d_in[7];
    const float* Wd     = (const float*)d_in[8];
    const float* bd     = (const float*)d_in[9];

    embw_kernel<<<(NTOK + 15) / 16, 256>>>(emb, W1x, b1);
    rnn_kernel<<<NBLK, THREADS>>>(tokens, W1h, W2x, W2h, b2, Wd, bd, (float*)d_out);
}